// round 4
// baseline (speedup 1.0000x reference)
#include <cuda_runtime.h>
#include <cuda_bf16.h>
#include <math.h>

#define B_   8192
#define F_   32
#define V_   64
#define C_   32
#define K_   8
#define KP_  7
#define FM1  31
#define EPS_ 1e-6f
#define VC_  (V_ * C_)          // 2048
#define VVC_ (V_ * V_ * C_)     // 131072
#define NFK  (FM1 * KP_)        // 217

// Scratch (no cudaMalloc allowed)
__device__ float g_T[F_ * VC_];                 // fused gather table = 256KB
__device__ float g_sexp[NFK * 4 * VC_];         // pair exp-sum partials = 7.1MB
__device__ __nv_bfloat16 g_ptb[(size_t)NFK * VVC_];  // bf16 shadow of pair_tables = 56.9MB

// ---------------------------------------------------------------------------
// Gate-row helper: gumbel-softmax weights for structure row i (0..30).
// ---------------------------------------------------------------------------
__device__ __forceinline__ void gate_row(int i, const float* __restrict__ sl,
                                         const float* __restrict__ un,
                                         float* __restrict__ wout) {
    int nv = 1 + ((i + 1 < KP_) ? (i + 1) : KP_);
    float gate[K_];
    float m = -1e30f;
#pragma unroll
    for (int k = 0; k < K_; k++) {
        if (k < nv) {
            float u = un[i * K_ + k];
            float g = -logf(-logf(u + EPS_) + EPS_);
            gate[k] = sl[i * K_ + k] + g;
            m = fmaxf(m, gate[k]);
        }
    }
    float s = 0.f;
#pragma unroll
    for (int k = 0; k < K_; k++)
        if (k < nv) { gate[k] = expf(gate[k] - m); s += gate[k]; }
    float inv = 1.f / s;
#pragma unroll
    for (int k = 0; k < K_; k++)
        wout[k] = (k < nv) ? gate[k] * inv : 0.f;
}

// ---------------------------------------------------------------------------
// Kernel 1 (fused prep): blocks 0..31 build T rows; blocks 32..1767 stream
// pair_tables once: accumulate exp-sums AND write the bf16 shadow copy.
// Quarter of the v-range per block for short chains / high parallelism.
// ---------------------------------------------------------------------------
__global__ void __launch_bounds__(256) k_prep(const float* __restrict__ cls,
                                              const float* __restrict__ t0,
                                              const float* __restrict__ st,
                                              const float* __restrict__ pt,
                                              const float* __restrict__ sl,
                                              const float* __restrict__ un) {
    int bid = blockIdx.x;
    int tid = threadIdx.x;

    if (bid >= 32) {
        int q    = bid - 32;             // 0..1735
        int fk   = q >> 3;               // 0..216
        int part = q & 1;                // half of the (v2,c) plane
        int vq   = (q >> 1) & 3;         // quarter of the v-range
        size_t slab = (size_t)fk * VVC_;
        int t = part * 256 + tid;        // float4 index within 512-wide plane
        const float4* base = (const float4*)(pt + slab) + vq * 16 * (VC_ / 4);
        uint2* outb = (uint2*)(g_ptb + slab) + vq * 16 * (VC_ / 4) + t;

        float s0 = 0.f, s1 = 0.f, s2 = 0.f, s3 = 0.f;
#pragma unroll 4
        for (int v = 0; v < 16; v++) {
            float4 r = __ldg(base + v * (VC_ / 4) + t);
            s0 += __expf(r.x); s1 += __expf(r.y);
            s2 += __expf(r.z); s3 += __expf(r.w);
            __nv_bfloat162 lo = __floats2bfloat162_rn(r.x, r.y);
            __nv_bfloat162 hi = __floats2bfloat162_rn(r.z, r.w);
            uint2 pk;
            pk.x = *(unsigned int*)&lo;
            pk.y = *(unsigned int*)&hi;
            outb[v * (VC_ / 4)] = pk;
        }
        float4 o; o.x = s0; o.y = s1; o.z = s2; o.w = s3;
        ((float4*)(g_sexp + (fk * 4 + vq) * VC_))[t] = o;
        return;
    }

    // ---- build T row j ----
    __shared__ float s_lse[C_];
    __shared__ float s_scalar;           // cl-lse (j==0) or w0 (j>0)
    int j = bid;

    if (j == 0) {
        if (tid == 0) {
            float m = -1e30f;
            for (int c = 0; c < C_; c++) m = fmaxf(m, cls[c]);
            float s = 0.f;
            for (int c = 0; c < C_; c++) s += expf(cls[c] - m);
            s_scalar = m + logf(s);
        }
        if (tid < C_) {
            float m = -1e30f;
            for (int v = 0; v < V_; v++) m = fmaxf(m, t0[v * C_ + tid]);
            float s = 0.f;
            for (int v = 0; v < V_; v++) s += expf(t0[v * C_ + tid] - m);
            s_lse[tid] = m + logf(s);
        }
        __syncthreads();
        for (int p = tid; p < VC_; p += blockDim.x) {
            int c = p & (C_ - 1);
            g_T[p] = (cls[c] - s_scalar) + (t0[p] - s_lse[c]);
        }
    } else {
        int f = j - 1;
        const float* stf = st + f * VC_;
        if (tid == 0) {
            float w[K_];
            gate_row(f, sl, un, w);
            s_scalar = w[0];
        }
        if (tid < C_) {
            float m = -1e30f;
            for (int v = 0; v < V_; v++) m = fmaxf(m, stf[v * C_ + tid]);
            float s = 0.f;
            for (int v = 0; v < V_; v++) s += expf(stf[v * C_ + tid] - m);
            s_lse[tid] = m + logf(s);
        }
        __syncthreads();
        float w0 = s_scalar;
        for (int p = tid; p < VC_; p += blockDim.x) {
            int c = p & (C_ - 1);
            g_T[j * VC_ + p] = w0 * (stf[p] - s_lse[c]);
        }
    }
}

// ---------------------------------------------------------------------------
// Kernel 2: fold weighted pair-LSE corrections into T (sum 4 partials + log).
// One thread per element (31*2048 = 63488 = 62 blocks x 1024 threads).
// ---------------------------------------------------------------------------
__global__ void __launch_bounds__(1024) k_fold(const float* __restrict__ sl,
                                               const float* __restrict__ un) {
    __shared__ float s_w[FM1 * K_];
    if (threadIdx.x < FM1) gate_row(threadIdx.x, sl, un, &s_w[threadIdx.x * K_]);
    __syncthreads();

    int e = blockIdx.x * 1024 + threadIdx.x;
    int m = e >> 11;                     // 0..30
    int p = e & (VC_ - 1);
    int jmax = (6 < 30 - m) ? 6 : (30 - m);
    float acc = 0.f;
#pragma unroll
    for (int jj = 0; jj < KP_; jj++) {
        if (jj <= jmax) {
            int i  = m + jj;
            int fk = i * KP_ + jj;
            float s = __ldg(&g_sexp[(fk * 4 + 0) * VC_ + p])
                    + __ldg(&g_sexp[(fk * 4 + 1) * VC_ + p])
                    + __ldg(&g_sexp[(fk * 4 + 2) * VC_ + p])
                    + __ldg(&g_sexp[(fk * 4 + 3) * VC_ + p]);
            acc = fmaf(s_w[i * K_ + jj + 1], __logf(s), acc);
        }
    }
    g_T[m * VC_ + p] -= acc;
}

// ---------------------------------------------------------------------------
// Kernel 3: main gather-accumulate. Two warps per batch element, lane = class.
// Pair gathers read the L2-resident bf16 shadow table (64B per warp-gather).
// ---------------------------------------------------------------------------
__global__ void __launch_bounds__(256) k_main(const int* __restrict__ x,
                                              const float* __restrict__ sl,
                                              const float* __restrict__ un,
                                              float* __restrict__ out) {
    __shared__ float s_w[FM1 * K_];
    __shared__ float s_part[8][C_];
    if (threadIdx.x < FM1) gate_row(threadIdx.x, sl, un, &s_w[threadIdx.x * K_]);
    __syncthreads();

    int warp = threadIdx.x >> 5;
    int lane = threadIdx.x & 31;
    int half = warp & 1;
    int b    = blockIdx.x * 4 + (warp >> 1);

    const int4* xr = (const int4*)(x + b * F_);
    float a0 = 0.f, a1 = 0.f, a2 = 0.f, a3 = 0.f;

    if (half == 0) {
        int xv[16];
#pragma unroll
        for (int q = 0; q < 4; q++) {
            int4 v = __ldg(&xr[q]);
            xv[4 * q + 0] = v.x; xv[4 * q + 1] = v.y;
            xv[4 * q + 2] = v.z; xv[4 * q + 3] = v.w;
        }
#pragma unroll
        for (int j = 0; j < 16; j++) {
            float t = __ldg(&g_T[(j * V_ + xv[j]) * C_ + lane]);
            if (j & 1) a1 += t; else a0 += t;
        }
#pragma unroll
        for (int i = 0; i < 15; i++) {
            int vsOff = xv[i + 1] * VC_;
            const int nk = (i + 1 < KP_) ? (i + 1) : KP_;
#pragma unroll
            for (int k = 0; k < nk; k++) {
                size_t off = (size_t)(i * KP_ + k) * VVC_ + vsOff + xv[i - k] * C_ + lane;
                float val  = __bfloat162float(__ldg(&g_ptb[off]));
                float w    = s_w[i * K_ + k + 1];
                if (k & 1) a3 = fmaf(w, val, a3); else a2 = fmaf(w, val, a2);
            }
        }
    } else {
        int xv[24];
#pragma unroll
        for (int q = 2; q < 8; q++) {
            int4 v = __ldg(&xr[q]);
            xv[4 * q - 8] = v.x; xv[4 * q - 7] = v.y;
            xv[4 * q - 6] = v.z; xv[4 * q - 5] = v.w;
        }
#pragma unroll
        for (int j = 16; j < 32; j++) {
            float t = __ldg(&g_T[(j * V_ + xv[j - 8]) * C_ + lane]);
            if (j & 1) a1 += t; else a0 += t;
        }
#pragma unroll
        for (int i = 15; i < FM1; i++) {
            int vsOff = xv[i + 1 - 8] * VC_;
#pragma unroll
            for (int k = 0; k < KP_; k++) {
                size_t off = (size_t)(i * KP_ + k) * VVC_ + vsOff + xv[i - k - 8] * C_ + lane;
                float val  = __bfloat162float(__ldg(&g_ptb[off]));
                float w    = s_w[i * K_ + k + 1];
                if (k & 1) a3 = fmaf(w, val, a3); else a2 = fmaf(w, val, a2);
            }
        }
    }

    float r = (a0 + a1) + (a2 + a3);
    s_part[warp][lane] = r;
    __syncthreads();
    if (half == 0)
        out[b * C_ + lane] = r + s_part[warp + 1][lane];
}

// ---------------------------------------------------------------------------
extern "C" void kernel_launch(void* const* d_in, const int* in_sizes, int n_in,
                              void* d_out, int out_size) {
    const int* x = (const int*)d_in[0];
    int idx = 1;
    if (in_sizes[1] == 1) idx = 2;   // skip scalar 'training' if present
    const float* cls = (const float*)d_in[idx++];
    const float* t0  = (const float*)d_in[idx++];
    const float* st  = (const float*)d_in[idx++];
    const float* pt  = (const float*)d_in[idx++];
    const float* sl  = (const float*)d_in[idx++];
    const float* un  = (const float*)d_in[idx++];
    float* out = (float*)d_out;

    k_prep<<<32 + NFK * 8, 256>>>(cls, t0, st, pt, sl, un);
    k_fold<<<62, 1024>>>(sl, un);
    k_main<<<B_ / 4, 256>>>(x, sl, un, out);
}

// round 5
// speedup vs baseline: 1.1640x; 1.1640x over previous
#include <cuda_runtime.h>
#include <cuda_bf16.h>
#include <math.h>

#define B_   8192
#define F_   32
#define V_   64
#define C_   32
#define K_   8
#define KP_  7
#define FM1  31
#define EPS_ 1e-6f
#define VC_  (V_ * C_)          // 2048
#define VVC_ (V_ * V_ * C_)     // 131072
#define NFK  (FM1 * KP_)        // 217

// Scratch (no cudaMalloc allowed)
__device__ float g_T[F_ * VC_];                 // fused gather table = 256KB
__device__ float g_sexp[NFK * 4 * VC_];         // pair exp-sum partials = 7.1MB
__device__ __nv_bfloat16 g_ptb[NFK * VVC_];     // bf16 shadow of pair_tables = 56.9MB

// ---------------------------------------------------------------------------
// Gate-row helper: gumbel-softmax weights for structure row i (0..30).
// ---------------------------------------------------------------------------
__device__ __forceinline__ void gate_row(int i, const float* __restrict__ sl,
                                         const float* __restrict__ un,
                                         float* __restrict__ wout) {
    int nv = 1 + ((i + 1 < KP_) ? (i + 1) : KP_);
    float gate[K_];
    float m = -1e30f;
#pragma unroll
    for (int k = 0; k < K_; k++) {
        if (k < nv) {
            float u = un[i * K_ + k];
            float g = -logf(-logf(u + EPS_) + EPS_);
            gate[k] = sl[i * K_ + k] + g;
            m = fmaxf(m, gate[k]);
        }
    }
    float s = 0.f;
#pragma unroll
    for (int k = 0; k < K_; k++)
        if (k < nv) { gate[k] = expf(gate[k] - m); s += gate[k]; }
    float inv = 1.f / s;
#pragma unroll
    for (int k = 0; k < K_; k++)
        wout[k] = (k < nv) ? gate[k] * inv : 0.f;
}

// ---------------------------------------------------------------------------
// Kernel 1 (fused prep): blocks 0..31 build T rows; blocks 32..1767 stream
// pair_tables ONCE (evict-first reads), produce exp-sum partials
// (write-through, single consumer) and the bf16 shadow (default policy ->
// stays L2-resident for k_main).
// ---------------------------------------------------------------------------
__global__ void __launch_bounds__(256) k_prep(const float* __restrict__ cls,
                                              const float* __restrict__ t0,
                                              const float* __restrict__ st,
                                              const float* __restrict__ pt,
                                              const float* __restrict__ sl,
                                              const float* __restrict__ un) {
    int bid = blockIdx.x;
    int tid = threadIdx.x;

    if (bid >= 32) {
        int q    = bid - 32;             // 0..1735
        int fk   = q >> 3;               // 0..216
        int part = q & 1;                // half of the (v2,c) plane
        int vq   = (q >> 1) & 3;         // quarter of the v-range
        size_t slab = (size_t)fk * VVC_;
        int t = part * 256 + tid;        // float4 index within 512-wide plane
        const float4* base = (const float4*)(pt + slab) + vq * 16 * (VC_ / 4);
        uint2* outb = (uint2*)(g_ptb + slab) + vq * 16 * (VC_ / 4) + t;

        float s0 = 0.f, s1 = 0.f, s2 = 0.f, s3 = 0.f;
#pragma unroll 4
        for (int v = 0; v < 16; v++) {
            float4 r = __ldcs(base + v * (VC_ / 4) + t);   // streaming read
            s0 += __expf(r.x); s1 += __expf(r.y);
            s2 += __expf(r.z); s3 += __expf(r.w);
            __nv_bfloat162 lo = __floats2bfloat162_rn(r.x, r.y);
            __nv_bfloat162 hi = __floats2bfloat162_rn(r.z, r.w);
            uint2 pk;
            pk.x = *(unsigned int*)&lo;
            pk.y = *(unsigned int*)&hi;
            outb[v * (VC_ / 4)] = pk;                      // default: L2-resident
        }
        float4 o; o.x = s0; o.y = s1; o.z = s2; o.w = s3;
        __stwt((float4*)(g_sexp + (fk * 4 + vq) * VC_) + t, o);  // write-through
        return;
    }

    // ---- build T row j ----
    __shared__ float s_lse[C_];
    __shared__ float s_scalar;           // cl-lse (j==0) or w0 (j>0)
    int j = bid;

    if (j == 0) {
        if (tid == 0) {
            float m = -1e30f;
            for (int c = 0; c < C_; c++) m = fmaxf(m, cls[c]);
            float s = 0.f;
            for (int c = 0; c < C_; c++) s += expf(cls[c] - m);
            s_scalar = m + logf(s);
        }
        if (tid < C_) {
            float m = -1e30f;
            for (int v = 0; v < V_; v++) m = fmaxf(m, t0[v * C_ + tid]);
            float s = 0.f;
            for (int v = 0; v < V_; v++) s += expf(t0[v * C_ + tid] - m);
            s_lse[tid] = m + logf(s);
        }
        __syncthreads();
        for (int p = tid; p < VC_; p += blockDim.x) {
            int c = p & (C_ - 1);
            g_T[p] = (cls[c] - s_scalar) + (t0[p] - s_lse[c]);
        }
    } else {
        int f = j - 1;
        const float* stf = st + f * VC_;
        if (tid == 0) {
            float w[K_];
            gate_row(f, sl, un, w);
            s_scalar = w[0];
        }
        if (tid < C_) {
            float m = -1e30f;
            for (int v = 0; v < V_; v++) m = fmaxf(m, stf[v * C_ + tid]);
            float s = 0.f;
            for (int v = 0; v < V_; v++) s += expf(stf[v * C_ + tid] - m);
            s_lse[tid] = m + logf(s);
        }
        __syncthreads();
        float w0 = s_scalar;
        for (int p = tid; p < VC_; p += blockDim.x) {
            int c = p & (C_ - 1);
            g_T[j * VC_ + p] = w0 * (stf[p] - s_lse[c]);
        }
    }
}

// ---------------------------------------------------------------------------
// Kernel 2: fold weighted pair-LSE corrections into T (sum 4 partials + log).
// Partials are read uncached (single use) to avoid evicting the bf16 table.
// ---------------------------------------------------------------------------
__global__ void __launch_bounds__(1024) k_fold(const float* __restrict__ sl,
                                               const float* __restrict__ un) {
    __shared__ float s_w[FM1 * K_];
    if (threadIdx.x < FM1) gate_row(threadIdx.x, sl, un, &s_w[threadIdx.x * K_]);
    __syncthreads();

    int e = blockIdx.x * 1024 + threadIdx.x;
    int m = e >> 11;                     // 0..30
    int p = e & (VC_ - 1);
    int jmax = (6 < 30 - m) ? 6 : (30 - m);
    float acc = 0.f;
#pragma unroll
    for (int jj = 0; jj < KP_; jj++) {
        if (jj <= jmax) {
            int i  = m + jj;
            int fk = i * KP_ + jj;
            float s = __ldcv(&g_sexp[(fk * 4 + 0) * VC_ + p])
                    + __ldcv(&g_sexp[(fk * 4 + 1) * VC_ + p])
                    + __ldcv(&g_sexp[(fk * 4 + 2) * VC_ + p])
                    + __ldcv(&g_sexp[(fk * 4 + 3) * VC_ + p]);
            acc = fmaf(s_w[i * K_ + jj + 1], __logf(s), acc);
        }
    }
    g_T[m * VC_ + p] -= acc;
}

// ---------------------------------------------------------------------------
// Kernel 3: main gather-accumulate. Two warps per batch element, lane = class.
// Pair gathers read the L2-resident bf16 shadow table (64B per warp-gather).
// ---------------------------------------------------------------------------
__global__ void __launch_bounds__(256) k_main(const int* __restrict__ x,
                                              const float* __restrict__ sl,
                                              const float* __restrict__ un,
                                              float* __restrict__ out) {
    __shared__ float s_w[FM1 * K_];
    __shared__ float s_part[8][C_];
    if (threadIdx.x < FM1) gate_row(threadIdx.x, sl, un, &s_w[threadIdx.x * K_]);
    __syncthreads();

    int warp = threadIdx.x >> 5;
    int lane = threadIdx.x & 31;
    int half = warp & 1;
    int b    = blockIdx.x * 4 + (warp >> 1);

    const int4* xr = (const int4*)(x + b * F_);
    float a0 = 0.f, a1 = 0.f, a2 = 0.f, a3 = 0.f;

    if (half == 0) {
        int xv[16];
#pragma unroll
        for (int q = 0; q < 4; q++) {
            int4 v = __ldg(&xr[q]);
            xv[4 * q + 0] = v.x; xv[4 * q + 1] = v.y;
            xv[4 * q + 2] = v.z; xv[4 * q + 3] = v.w;
        }
#pragma unroll
        for (int j = 0; j < 16; j++) {
            float t = __ldg(&g_T[(j * V_ + xv[j]) * C_ + lane]);
            if (j & 1) a1 += t; else a0 += t;
        }
#pragma unroll
        for (int i = 0; i < 15; i++) {
            int vsOff = xv[i + 1] * VC_;
            const int nk = (i + 1 < KP_) ? (i + 1) : KP_;
#pragma unroll
            for (int k = 0; k < nk; k++) {
                int off   = (i * KP_ + k) * VVC_ + vsOff + xv[i - k] * C_ + lane;
                float val = __bfloat162float(__ldg(&g_ptb[off]));
                float w   = s_w[i * K_ + k + 1];
                if (k & 1) a3 = fmaf(w, val, a3); else a2 = fmaf(w, val, a2);
            }
        }
    } else {
        int xv[24];
#pragma unroll
        for (int q = 2; q < 8; q++) {
            int4 v = __ldg(&xr[q]);
            xv[4 * q - 8] = v.x; xv[4 * q - 7] = v.y;
            xv[4 * q - 6] = v.z; xv[4 * q - 5] = v.w;
        }
#pragma unroll
        for (int j = 16; j < 32; j++) {
            float t = __ldg(&g_T[(j * V_ + xv[j - 8]) * C_ + lane]);
            if (j & 1) a1 += t; else a0 += t;
        }
#pragma unroll
        for (int i = 15; i < FM1; i++) {
            int vsOff = xv[i + 1 - 8] * VC_;
#pragma unroll
            for (int k = 0; k < KP_; k++) {
                int off   = (i * KP_ + k) * VVC_ + vsOff + xv[i - k - 8] * C_ + lane;
                float val = __bfloat162float(__ldg(&g_ptb[off]));
                float w   = s_w[i * K_ + k + 1];
                if (k & 1) a3 = fmaf(w, val, a3); else a2 = fmaf(w, val, a2);
            }
        }
    }

    float r = (a0 + a1) + (a2 + a3);
    s_part[warp][lane] = r;
    __syncthreads();
    if (half == 0)
        out[b * C_ + lane] = r + s_part[warp + 1][lane];
}

// ---------------------------------------------------------------------------
extern "C" void kernel_launch(void* const* d_in, const int* in_sizes, int n_in,
                              void* d_out, int out_size) {
    const int* x = (const int*)d_in[0];
    int idx = 1;
    if (in_sizes[1] == 1) idx = 2;   // skip scalar 'training' if present
    const float* cls = (const float*)d_in[idx++];
    const float* t0  = (const float*)d_in[idx++];
    const float* st  = (const float*)d_in[idx++];
    const float* pt  = (const float*)d_in[idx++];
    const float* sl  = (const float*)d_in[idx++];
    const float* un  = (const float*)d_in[idx++];
    float* out = (float*)d_out;

    k_prep<<<32 + NFK * 8, 256>>>(cls, t0, st, pt, sl, un);
    k_fold<<<62, 1024>>>(sl, un);
    k_main<<<B_ / 4, 256>>>(x, sl, un, out);
}

// round 6
// speedup vs baseline: 1.4058x; 1.2077x over previous
#include <cuda_runtime.h>
#include <math.h>

#define B_   8192
#define F_   32
#define V_   64
#define C_   32
#define K_   8
#define KP_  7
#define FM1  31
#define EPS_ 1e-6f
#define VC_  (V_ * C_)          // 2048
#define VVC_ (V_ * V_ * C_)     // 131072
#define NFK  (FM1 * KP_)        // 217

// Scratch (no cudaMalloc allowed)
__device__ float g_T[F_ * VC_];             // fused gather table = 256KB
__device__ float g_sexp[NFK * 4 * VC_];     // pair exp-sum partials = 7.1MB
__device__ float g_psum[B_ * C_];           // per-element pair partial sums = 1MB

// ---------------------------------------------------------------------------
// Gate-row helper: gumbel-softmax weights for structure row i (0..30).
// ---------------------------------------------------------------------------
__device__ __forceinline__ void gate_row(int i, const float* __restrict__ sl,
                                         const float* __restrict__ un,
                                         float* __restrict__ wout) {
    int nv = 1 + ((i + 1 < KP_) ? (i + 1) : KP_);
    float gate[K_];
    float m = -1e30f;
#pragma unroll
    for (int k = 0; k < K_; k++) {
        if (k < nv) {
            float u = un[i * K_ + k];
            float g = -logf(-logf(u + EPS_) + EPS_);
            gate[k] = sl[i * K_ + k] + g;
            m = fmaxf(m, gate[k]);
        }
    }
    float s = 0.f;
#pragma unroll
    for (int k = 0; k < K_; k++)
        if (k < nv) { gate[k] = expf(gate[k] - m); s += gate[k]; }
    float inv = 1.f / s;
#pragma unroll
    for (int k = 0; k < K_; k++)
        wout[k] = (k < nv) ? gate[k] * inv : 0.f;
}

// ---------------------------------------------------------------------------
// Kernel A (stream B): pair gathers only. Two warps per batch element,
// balanced split (i=0..16 : 98 gathers, i=17..30 : 98 gathers).
// ---------------------------------------------------------------------------
__global__ void __launch_bounds__(256) k_pairs(const int* __restrict__ x,
                                               const float* __restrict__ pt,
                                               const float* __restrict__ sl,
                                               const float* __restrict__ un) {
    __shared__ float s_w[FM1 * K_];
    __shared__ float s_part[8][C_];
    if (threadIdx.x < FM1) gate_row(threadIdx.x, sl, un, &s_w[threadIdx.x * K_]);
    __syncthreads();

    int warp = threadIdx.x >> 5;
    int lane = threadIdx.x & 31;
    int half = warp & 1;
    int b    = blockIdx.x * 4 + (warp >> 1);

    const int4* xr = (const int4*)(x + b * F_);
    float a0 = 0.f, a1 = 0.f;

    if (half == 0) {
        // needs x[0..17]
        int xv[20];
#pragma unroll
        for (int q = 0; q < 5; q++) {
            int4 v = __ldg(&xr[q]);
            xv[4 * q + 0] = v.x; xv[4 * q + 1] = v.y;
            xv[4 * q + 2] = v.z; xv[4 * q + 3] = v.w;
        }
#pragma unroll
        for (int i = 0; i < 17; i++) {
            int vsOff = xv[i + 1] * VC_;
            const int nk = (i + 1 < KP_) ? (i + 1) : KP_;
#pragma unroll
            for (int k = 0; k < nk; k++) {
                int off   = (i * KP_ + k) * VVC_ + vsOff + xv[i - k] * C_ + lane;
                float val = __ldcg(&pt[off]);
                float w   = s_w[i * K_ + k + 1];
                if (k & 1) a1 = fmaf(w, val, a1); else a0 = fmaf(w, val, a0);
            }
        }
    } else {
        // needs x[11..31]; base offset 8
        int xv[24];
#pragma unroll
        for (int q = 2; q < 8; q++) {
            int4 v = __ldg(&xr[q]);
            xv[4 * q - 8] = v.x; xv[4 * q - 7] = v.y;
            xv[4 * q - 6] = v.z; xv[4 * q - 5] = v.w;
        }
#pragma unroll
        for (int i = 17; i < FM1; i++) {
            int vsOff = xv[i + 1 - 8] * VC_;
#pragma unroll
            for (int k = 0; k < KP_; k++) {
                int off   = (i * KP_ + k) * VVC_ + vsOff + xv[i - k - 8] * C_ + lane;
                float val = __ldcg(&pt[off]);
                float w   = s_w[i * K_ + k + 1];
                if (k & 1) a1 = fmaf(w, val, a1); else a0 = fmaf(w, val, a0);
            }
        }
    }

    float r = a0 + a1;
    s_part[warp][lane] = r;
    __syncthreads();
    if (half == 0)
        g_psum[b * C_ + lane] = r + s_part[warp + 1][lane];
}

// ---------------------------------------------------------------------------
// Kernel B (stream 0): prep. Blocks 0..31 build T rows; blocks 32..1767
// compute pair-table exp-sum partials (float4, quarter v-range per block).
// ---------------------------------------------------------------------------
__global__ void __launch_bounds__(256) k_prep(const float* __restrict__ cls,
                                              const float* __restrict__ t0,
                                              const float* __restrict__ st,
                                              const float* __restrict__ pt,
                                              const float* __restrict__ sl,
                                              const float* __restrict__ un) {
    int bid = blockIdx.x;
    int tid = threadIdx.x;

    if (bid >= 32) {
        int q    = bid - 32;             // 0..1735
        int fk   = q >> 3;               // 0..216
        int part = q & 1;                // half of the (v2,c) plane
        int vq   = (q >> 1) & 3;         // quarter of the v-range
        const float4* base = (const float4*)(pt + (size_t)fk * VVC_)
                             + vq * 16 * (VC_ / 4);
        int t = part * 256 + tid;
        float s0 = 0.f, s1 = 0.f, s2 = 0.f, s3 = 0.f;
#pragma unroll
        for (int v = 0; v < 16; v++) {
            float4 r = __ldg(base + v * (VC_ / 4) + t);
            s0 += __expf(r.x); s1 += __expf(r.y);
            s2 += __expf(r.z); s3 += __expf(r.w);
        }
        float4 o; o.x = s0; o.y = s1; o.z = s2; o.w = s3;
        ((float4*)(g_sexp + (fk * 4 + vq) * VC_))[t] = o;
        return;
    }

    __shared__ float s_lse[C_];
    __shared__ float s_scalar;
    int j = bid;

    if (j == 0) {
        if (tid == 0) {
            float m = -1e30f;
            for (int c = 0; c < C_; c++) m = fmaxf(m, cls[c]);
            float s = 0.f;
            for (int c = 0; c < C_; c++) s += expf(cls[c] - m);
            s_scalar = m + logf(s);
        }
        if (tid < C_) {
            float m = -1e30f;
            for (int v = 0; v < V_; v++) m = fmaxf(m, t0[v * C_ + tid]);
            float s = 0.f;
            for (int v = 0; v < V_; v++) s += expf(t0[v * C_ + tid] - m);
            s_lse[tid] = m + logf(s);
        }
        __syncthreads();
        for (int p = tid; p < VC_; p += blockDim.x) {
            int c = p & (C_ - 1);
            g_T[p] = (cls[c] - s_scalar) + (t0[p] - s_lse[c]);
        }
    } else {
        int f = j - 1;
        const float* stf = st + f * VC_;
        if (tid == 0) {
            float w[K_];
            gate_row(f, sl, un, w);
            s_scalar = w[0];
        }
        if (tid < C_) {
            float m = -1e30f;
            for (int v = 0; v < V_; v++) m = fmaxf(m, stf[v * C_ + tid]);
            float s = 0.f;
            for (int v = 0; v < V_; v++) s += expf(stf[v * C_ + tid] - m);
            s_lse[tid] = m + logf(s);
        }
        __syncthreads();
        float w0 = s_scalar;
        for (int p = tid; p < VC_; p += blockDim.x) {
            int c = p & (C_ - 1);
            g_T[j * VC_ + p] = w0 * (stf[p] - s_lse[c]);
        }
    }
}

// ---------------------------------------------------------------------------
// Kernel C (stream 0): fold weighted pair-LSE corrections into T.
// ---------------------------------------------------------------------------
__global__ void __launch_bounds__(1024) k_fold(const float* __restrict__ sl,
                                               const float* __restrict__ un) {
    __shared__ float s_w[FM1 * K_];
    if (threadIdx.x < FM1) gate_row(threadIdx.x, sl, un, &s_w[threadIdx.x * K_]);
    __syncthreads();

    int e = blockIdx.x * 1024 + threadIdx.x;
    int m = e >> 11;
    int p = e & (VC_ - 1);
    int jmax = (6 < 30 - m) ? 6 : (30 - m);
    float acc = 0.f;
#pragma unroll
    for (int jj = 0; jj < KP_; jj++) {
        if (jj <= jmax) {
            int i  = m + jj;
            int fk = i * KP_ + jj;
            float s = __ldg(&g_sexp[(fk * 4 + 0) * VC_ + p])
                    + __ldg(&g_sexp[(fk * 4 + 1) * VC_ + p])
                    + __ldg(&g_sexp[(fk * 4 + 2) * VC_ + p])
                    + __ldg(&g_sexp[(fk * 4 + 3) * VC_ + p]);
            acc = fmaf(s_w[i * K_ + jj + 1], __logf(s), acc);
        }
    }
    g_T[m * VC_ + p] -= acc;
}

// ---------------------------------------------------------------------------
// Kernel D (join): T gathers + add pair partials. One warp per element.
// ---------------------------------------------------------------------------
__global__ void __launch_bounds__(256) k_mainT(const int* __restrict__ x,
                                               float* __restrict__ out) {
    int warp = threadIdx.x >> 5;
    int lane = threadIdx.x & 31;
    int b    = blockIdx.x * 8 + warp;

    const int4* xr = (const int4*)(x + b * F_);
    int xv[F_];
#pragma unroll
    for (int q = 0; q < 8; q++) {
        int4 v = __ldg(&xr[q]);
        xv[4 * q + 0] = v.x; xv[4 * q + 1] = v.y;
        xv[4 * q + 2] = v.z; xv[4 * q + 3] = v.w;
    }
    float a0 = 0.f, a1 = 0.f;
#pragma unroll
    for (int j = 0; j < F_; j++) {
        float t = __ldg(&g_T[(j * V_ + xv[j]) * C_ + lane]);
        if (j & 1) a1 += t; else a0 += t;
    }
    out[b * C_ + lane] = (a0 + a1) + g_psum[b * C_ + lane];
}

// ---------------------------------------------------------------------------
extern "C" void kernel_launch(void* const* d_in, const int* in_sizes, int n_in,
                              void* d_out, int out_size) {
    const int* x = (const int*)d_in[0];
    int idx = 1;
    if (in_sizes[1] == 1) idx = 2;   // skip scalar 'training' if present
    const float* cls = (const float*)d_in[idx++];
    const float* t0  = (const float*)d_in[idx++];
    const float* st  = (const float*)d_in[idx++];
    const float* pt  = (const float*)d_in[idx++];
    const float* sl  = (const float*)d_in[idx++];
    const float* un  = (const float*)d_in[idx++];
    float* out = (float*)d_out;

    // One-time side stream + events (host-side resources, not device memory).
    static cudaStream_t s2 = nullptr;
    static cudaEvent_t evFork = nullptr, evJoin = nullptr;
    if (s2 == nullptr) {
        cudaStreamCreateWithFlags(&s2, cudaStreamNonBlocking);
        cudaEventCreateWithFlags(&evFork, cudaEventDisableTiming);
        cudaEventCreateWithFlags(&evJoin, cudaEventDisableTiming);
    }

    // Fork: pair gathers run concurrently with prep+fold.
    cudaEventRecord(evFork, 0);
    cudaStreamWaitEvent(s2, evFork, 0);
    k_pairs<<<B_ / 4, 256, 0, s2>>>(x, pt, sl, un);
    cudaEventRecord(evJoin, s2);

    k_prep<<<32 + NFK * 8, 256>>>(cls, t0, st, pt, sl, un);
    k_fold<<<62, 1024>>>(sl, un);

    // Join, then finish with the T gathers.
    cudaStreamWaitEvent(0, evJoin, 0);
    k_mainT<<<B_ / 8, 256>>>(x, out);
}

// round 7
// speedup vs baseline: 1.5066x; 1.0717x over previous
#include <cuda_runtime.h>
#include <math.h>

#define B_   8192
#define F_   32
#define V_   64
#define C_   32
#define K_   8
#define KP_  7
#define FM1  31
#define EPS_ 1e-6f
#define VC_  (V_ * C_)          // 2048
#define VVC_ (V_ * V_ * C_)     // 131072
#define NFK  (FM1 * KP_)        // 217

#define NPREP  (32 + NFK * 8)   // 1768 prep-role blocks
#define NPAIRS (B_ / 4)         // 2048 pairs-role blocks
#define NINTER (2 * NPREP)      // 3536 interleaved region

// Scratch (no cudaMalloc allowed)
__device__ float g_T[F_ * VC_];             // fused gather table = 256KB
__device__ float g_sexp[NFK * 4 * VC_];     // pair exp-sum partials = 7.1MB
__device__ float g_psum[B_ * C_];           // per-element pair partial sums = 1MB

// ---------------------------------------------------------------------------
// Gate-row helper: gumbel-softmax weights for structure row i (0..30).
// ---------------------------------------------------------------------------
__device__ __forceinline__ void gate_row(int i, const float* __restrict__ sl,
                                         const float* __restrict__ un,
                                         float* __restrict__ wout) {
    int nv = 1 + ((i + 1 < KP_) ? (i + 1) : KP_);
    float gate[K_];
    float m = -1e30f;
#pragma unroll
    for (int k = 0; k < K_; k++) {
        if (k < nv) {
            float u = un[i * K_ + k];
            float g = -logf(-logf(u + EPS_) + EPS_);
            gate[k] = sl[i * K_ + k] + g;
            m = fmaxf(m, gate[k]);
        }
    }
    float s = 0.f;
#pragma unroll
    for (int k = 0; k < K_; k++)
        if (k < nv) { gate[k] = expf(gate[k] - m); s += gate[k]; }
    float inv = 1.f / s;
#pragma unroll
    for (int k = 0; k < K_; k++)
        wout[k] = (k < nv) ? gate[k] * inv : 0.f;
}

// ---------------------------------------------------------------------------
// Fused kernel: interleaved block roles so DRAM-streaming (prep) and
// latency-bound gathers (pairs) co-reside on every SM.
//   bid < NINTER : even -> prep(bid/2), odd -> pairs(bid/2)
//   bid >= NINTER: pairs(NPREP + bid - NINTER)
// prep(r): r<32 builds T row r; else exp-sum slab q=r-32 (8 blocks per fk).
// pairs(p): 4 batch elements, 2 warps each (98 gathers per warp).
// ---------------------------------------------------------------------------
__global__ void __launch_bounds__(256) k_fused(const int* __restrict__ x,
                                               const float* __restrict__ cls,
                                               const float* __restrict__ t0,
                                               const float* __restrict__ st,
                                               const float* __restrict__ pt,
                                               const float* __restrict__ sl,
                                               const float* __restrict__ un) {
    int bid = blockIdx.x;
    int tid = threadIdx.x;
    int role, ridx;
    if (bid < NINTER) { role = bid & 1; ridx = bid >> 1; }
    else              { role = 1;       ridx = NPREP + (bid - NINTER); }

    if (role == 1) {
        // =================== pairs role ===================
        __shared__ float s_w[FM1 * K_];
        __shared__ float s_part[8][C_];
        if (tid < FM1) gate_row(tid, sl, un, &s_w[tid * K_]);
        __syncthreads();

        int warp = tid >> 5;
        int lane = tid & 31;
        int half = warp & 1;
        int b    = ridx * 4 + (warp >> 1);

        const int4* xr = (const int4*)(x + b * F_);
        float a0 = 0.f, a1 = 0.f;

        if (half == 0) {
            int xv[20];
#pragma unroll
            for (int q = 0; q < 5; q++) {
                int4 v = __ldg(&xr[q]);
                xv[4 * q + 0] = v.x; xv[4 * q + 1] = v.y;
                xv[4 * q + 2] = v.z; xv[4 * q + 3] = v.w;
            }
#pragma unroll
            for (int i = 0; i < 17; i++) {
                int vsOff = xv[i + 1] * VC_;
                const int nk = (i + 1 < KP_) ? (i + 1) : KP_;
#pragma unroll
                for (int k = 0; k < nk; k++) {
                    int off   = (i * KP_ + k) * VVC_ + vsOff + xv[i - k] * C_ + lane;
                    float val = __ldg(&pt[off]);
                    float w   = s_w[i * K_ + k + 1];
                    if (k & 1) a1 = fmaf(w, val, a1); else a0 = fmaf(w, val, a0);
                }
            }
        } else {
            int xv[24];
#pragma unroll
            for (int q = 2; q < 8; q++) {
                int4 v = __ldg(&xr[q]);
                xv[4 * q - 8] = v.x; xv[4 * q - 7] = v.y;
                xv[4 * q - 6] = v.z; xv[4 * q - 5] = v.w;
            }
#pragma unroll
            for (int i = 17; i < FM1; i++) {
                int vsOff = xv[i + 1 - 8] * VC_;
#pragma unroll
                for (int k = 0; k < KP_; k++) {
                    int off   = (i * KP_ + k) * VVC_ + vsOff + xv[i - k - 8] * C_ + lane;
                    float val = __ldg(&pt[off]);
                    float w   = s_w[i * K_ + k + 1];
                    if (k & 1) a1 = fmaf(w, val, a1); else a0 = fmaf(w, val, a0);
                }
            }
        }

        float r = a0 + a1;
        s_part[warp][lane] = r;
        __syncthreads();
        if (half == 0)
            g_psum[b * C_ + lane] = r + s_part[warp + 1][lane];
        return;
    }

    // =================== prep role ===================
    if (ridx >= 32) {
        int q    = ridx - 32;            // 0..1735
        int fk   = q >> 3;               // 0..216
        int part = q & 1;
        int vq   = (q >> 1) & 3;
        const float4* base = (const float4*)(pt + (size_t)fk * VVC_)
                             + vq * 16 * (VC_ / 4);
        int t = part * 256 + tid;
        float s0 = 0.f, s1 = 0.f, s2 = 0.f, s3 = 0.f;
#pragma unroll
        for (int v = 0; v < 16; v++) {
            float4 r = __ldg(base + v * (VC_ / 4) + t);
            s0 += __expf(r.x); s1 += __expf(r.y);
            s2 += __expf(r.z); s3 += __expf(r.w);
        }
        float4 o; o.x = s0; o.y = s1; o.z = s2; o.w = s3;
        ((float4*)(g_sexp + (fk * 4 + vq) * VC_))[t] = o;
        return;
    }

    __shared__ float s_lse[C_];
    __shared__ float s_scalar;
    int j = ridx;

    if (j == 0) {
        if (tid == 0) {
            float m = -1e30f;
            for (int c = 0; c < C_; c++) m = fmaxf(m, cls[c]);
            float s = 0.f;
            for (int c = 0; c < C_; c++) s += expf(cls[c] - m);
            s_scalar = m + logf(s);
        }
        if (tid < C_) {
            float m = -1e30f;
            for (int v = 0; v < V_; v++) m = fmaxf(m, t0[v * C_ + tid]);
            float s = 0.f;
            for (int v = 0; v < V_; v++) s += expf(t0[v * C_ + tid] - m);
            s_lse[tid] = m + logf(s);
        }
        __syncthreads();
        for (int p = tid; p < VC_; p += blockDim.x) {
            int c = p & (C_ - 1);
            g_T[p] = (cls[c] - s_scalar) + (t0[p] - s_lse[c]);
        }
    } else {
        int f = j - 1;
        const float* stf = st + f * VC_;
        if (tid == 0) {
            float w[K_];
            gate_row(f, sl, un, w);
            s_scalar = w[0];
        }
        if (tid < C_) {
            float m = -1e30f;
            for (int v = 0; v < V_; v++) m = fmaxf(m, stf[v * C_ + tid]);
            float s = 0.f;
            for (int v = 0; v < V_; v++) s += expf(stf[v * C_ + tid] - m);
            s_lse[tid] = m + logf(s);
        }
        __syncthreads();
        float w0 = s_scalar;
        for (int p = tid; p < VC_; p += blockDim.x) {
            int c = p & (C_ - 1);
            g_T[j * VC_ + p] = w0 * (stf[p] - s_lse[c]);
        }
    }
}

// ---------------------------------------------------------------------------
// Kernel 2: fold weighted pair-LSE corrections into T (sum 4 partials + log).
// ---------------------------------------------------------------------------
__global__ void __launch_bounds__(1024) k_fold(const float* __restrict__ sl,
                                               const float* __restrict__ un) {
    __shared__ float s_w[FM1 * K_];
    if (threadIdx.x < FM1) gate_row(threadIdx.x, sl, un, &s_w[threadIdx.x * K_]);
    __syncthreads();

    int e = blockIdx.x * 1024 + threadIdx.x;
    int m = e >> 11;
    int p = e & (VC_ - 1);
    int jmax = (6 < 30 - m) ? 6 : (30 - m);
    float acc = 0.f;
#pragma unroll
    for (int jj = 0; jj < KP_; jj++) {
        if (jj <= jmax) {
            int i  = m + jj;
            int fk = i * KP_ + jj;
            float s = __ldg(&g_sexp[(fk * 4 + 0) * VC_ + p])
                    + __ldg(&g_sexp[(fk * 4 + 1) * VC_ + p])
                    + __ldg(&g_sexp[(fk * 4 + 2) * VC_ + p])
                    + __ldg(&g_sexp[(fk * 4 + 3) * VC_ + p]);
            acc = fmaf(s_w[i * K_ + jj + 1], __logf(s), acc);
        }
    }
    g_T[m * VC_ + p] -= acc;
}

// ---------------------------------------------------------------------------
// Kernel 3: T gathers + add pair partials. TWO warps per element (16-deep
// chains), smem combine.
// ---------------------------------------------------------------------------
__global__ void __launch_bounds__(256) k_mainT(const int* __restrict__ x,
                                               float* __restrict__ out) {
    __shared__ float s_part[8][C_];
    int warp = threadIdx.x >> 5;
    int lane = threadIdx.x & 31;
    int half = warp & 1;
    int b    = blockIdx.x * 4 + (warp >> 1);

    const int4* xr = (const int4*)(x + b * F_) + half * 4;
    int xv[16];
#pragma unroll
    for (int q = 0; q < 4; q++) {
        int4 v = __ldg(&xr[q]);
        xv[4 * q + 0] = v.x; xv[4 * q + 1] = v.y;
        xv[4 * q + 2] = v.z; xv[4 * q + 3] = v.w;
    }
    int jbase = half * 16;
    float a0 = 0.f, a1 = 0.f;
#pragma unroll
    for (int j = 0; j < 16; j++) {
        float t = __ldg(&g_T[((jbase + j) * V_ + xv[j]) * C_ + lane]);
        if (j & 1) a1 += t; else a0 += t;
    }
    float r = a0 + a1;
    s_part[warp][lane] = r;
    __syncthreads();
    if (half == 0)
        out[b * C_ + lane] = r + s_part[warp + 1][lane] + g_psum[b * C_ + lane];
}

// ---------------------------------------------------------------------------
extern "C" void kernel_launch(void* const* d_in, const int* in_sizes, int n_in,
                              void* d_out, int out_size) {
    const int* x = (const int*)d_in[0];
    int idx = 1;
    if (in_sizes[1] == 1) idx = 2;   // skip scalar 'training' if present
    const float* cls = (const float*)d_in[idx++];
    const float* t0  = (const float*)d_in[idx++];
    const float* st  = (const float*)d_in[idx++];
    const float* pt  = (const float*)d_in[idx++];
    const float* sl  = (const float*)d_in[idx++];
    const float* un  = (const float*)d_in[idx++];
    float* out = (float*)d_out;

    k_fused<<<NINTER + (NPAIRS - NPREP), 256>>>(x, cls, t0, st, pt, sl, un);
    k_fold<<<62, 1024>>>(sl, un);
    k_mainT<<<B_ / 4, 256>>>(x, out);
}